// round 14
// baseline (speedup 1.0000x reference)
#include <cuda_runtime.h>
#include <cuda_fp16.h>
#include <stdint.h>
#include <math.h>

#define BSZ 512
#define TIN 128
#define FDIM 64
#define UNITS 1024
#define OUT_STEPS 32
#define NSTEPS 159           // TIN + OUT_STEPS - 1 LSTM steps
#define NGATE 4096           // 4*UNITS, gate-interleaved: n' = u*4 + g
#define KTOT 1088            // 1024 (h) + 64 (x)
#define NCHUNK 9             // 8 h-chunks (K=128 each) + 1 x half-chunk (K=64)
#define NBLK 256

// ---------------- persistent device scratch (allocation-free) ----------------
__device__ __half g_Wt[(size_t)NGATE * KTOT];     // fp16 weights, [n'][k] K-major
__device__ float  g_b2[NGATE];                    // bias reordered to n'
__device__ __half g_in[(size_t)BSZ * TIN * FDIM]; // fp16 inputs
__device__ __half g_hA[(size_t)BSZ * UNITS];
__device__ __half g_hB[(size_t)BSZ * UNITS];
__device__ float  g_hf32[(size_t)BSZ * UNITS];    // fp32 h (decode region only)
__device__ __half g_xd[(size_t)BSZ * FDIM];       // decode input = fp16(pred)
__device__ unsigned g_bar1[8 * 32];               // level-1 counters (1/batch lane, 128B apart)
__device__ unsigned g_bar2[32];                   // [0]=root count, [16]=generation

__device__ __forceinline__ uint32_t smem_u32(const void* p) {
    uint32_t a;
    asm("{ .reg .u64 t; cvta.to.shared.u64 t, %1; cvt.u32.u64 %0, t; }" : "=r"(a) : "l"(p));
    return a;
}
__device__ __forceinline__ void cp16(uint32_t saddr, const void* g) {
    asm volatile("cp.async.cg.shared.global [%0], [%1], 16;" :: "r"(saddr), "l"(g));
}
__device__ __forceinline__ void cp_commit() {
    asm volatile("cp.async.commit_group;" ::: "memory");
}
template <int N>
__device__ __forceinline__ void cp_wait() {
    asm volatile("cp.async.wait_group %0;" :: "n"(N) : "memory");
}
__device__ __forceinline__ void ldm4(uint32_t* r, uint32_t addr) {
    asm volatile("ldmatrix.sync.aligned.m8n8.x4.shared.b16 {%0,%1,%2,%3}, [%4];"
        : "=r"(r[0]), "=r"(r[1]), "=r"(r[2]), "=r"(r[3]) : "r"(addr));
}
// mma.sync m16n8k16 row.col fp16 -> f32 (baseline PTX)
__device__ __forceinline__ void mma16816(float* d, const uint32_t* a, const uint32_t* b) {
    asm volatile(
        "mma.sync.aligned.m16n8k16.row.col.f32.f16.f16.f32 "
        "{%0,%1,%2,%3}, {%4,%5,%6,%7}, {%8,%9}, {%0,%1,%2,%3};"
        : "+f"(d[0]), "+f"(d[1]), "+f"(d[2]), "+f"(d[3])
        : "r"(a[0]), "r"(a[1]), "r"(a[2]), "r"(a[3]), "r"(b[0]), "r"(b[1]));
}
__device__ __forceinline__ float sigm(float x) {
    return __fdividef(1.0f, 1.0f + __expf(-x));
}
__device__ __forceinline__ float ftanh(float x) {
    return __fdividef(2.0f, 1.0f + __expf(-2.0f * x)) - 1.0f;
}

#define SWZ(o) ((o) ^ (((o) >> 3) & 0x70))

// ---------------- SMEM layout ----------------
// [0,512): bias (128 floats).
// Stage (48 KB): A = 2 subs of 8K (64 rows x 128B) @0, @8192;
//                B = 2 subs of 16K (128 rows x 128B) @16384, @32768.
// Two stages. Chunk c -> stage c&1 (last chunk c=8 -> stage 0).
// z scratch (64x132 f32 = 33792 B) overlays stage 1.
#define A_SUB_B 8192
#define A_TILE_B 16384
#define B_SUB_B 16384
#define STAGE_B 49152
#define SM_STG 512
#define SM_ZS (SM_STG + STAGE_B)
#define SM_TOTAL (SM_STG + 2 * STAGE_B)   // 98816 (2 CTAs/SM: 197KB < 228KB)

// Two-level barrier: 32 arrivals per batch-lane counter, then 8 on the root.
__device__ __forceinline__ void grid_barrier(int bx, unsigned target) {
    __threadfence();
    __syncthreads();
    if (threadIdx.x == 0) {
        if (atomicAdd(&g_bar1[bx * 32], 1u) == 31u) {
            atomicExch(&g_bar1[bx * 32], 0u);
            if (atomicAdd(&g_bar2[0], 1u) == 7u) {
                atomicExch(&g_bar2[0], 0u);
                __threadfence();
                atomicExch(&g_bar2[16], target);
            }
        }
        while (((volatile unsigned*)g_bar2)[16] < target) __nanosleep(32);
        __threadfence();
    }
    __syncthreads();
}

__global__ __launch_bounds__(128, 2)
void lstm_persist(const float* __restrict__ Wd,
                  const float* __restrict__ bd,
                  float* __restrict__ out)
{
    extern __shared__ char smem[];
    const uint32_t sbase = smem_u32(smem);
    const int tid = threadIdx.x, wid = tid >> 5, lane = tid & 31;
    const int warp_m = wid >> 1;            // 0..1 -> rows warp_m*32
    const int warp_n = wid & 1;             // 0..1 -> cols warp_n*64
    const int bx = blockIdx.x;
    const int m0 = bx * 64;                 // batch tile (M=64)
    const int n0 = blockIdx.y * 128;        // gate-interleaved column base (N=128)
    const int u0 = blockIdx.y * 32;
    const int flat = blockIdx.y * gridDim.x + bx;

    ((float*)smem)[tid] = g_b2[n0 + tid];

    const __half* __restrict__ Bw = g_Wt + (size_t)n0 * KTOT;

    const int a_r  = warp_m * 32 + (lane & 15);
    const int a_cs = (lane >> 4) * 16;
    const int b_r  = warp_n * 64 + (lane & 7) + ((lane >> 4) << 3);
    const int b_cs = ((lane >> 3) & 1) * 16;

    unsigned lgen = 0;

    // persistent cell state: this (CTA, thread) owns the same 16 units forever
    float cf[16];
    #pragma unroll
    for (int j = 0; j < 16; ++j) cf[j] = 0.f;

    float acc[2][8][4];   // warp tile 32x64: mf 0..1, nf 0..7

    // W loader: chunk c covers k = c*128 + sub*64 (c=8: one sub only, k=1024..1087)
    auto issueW = [&](int c, int st) {
        const int nsub = (c == 8) ? 1 : 2;
        for (int s = 0; s < nsub; ++s) {
            const uint32_t sb = sbase + SM_STG + st * STAGE_B + A_TILE_B + s * B_SUB_B;
            const __half* wp = Bw + (size_t)(c * 128 + s * 64);
            #pragma unroll
            for (int i = 0; i < 8; ++i) {
                const int idx = i * 128 + tid;
                const int row = idx >> 3, ch = idx & 7;
                cp16(sb + SWZ(row * 128 + ch * 16), wp + (size_t)row * KTOT + ch * 8);
            }
        }
    };

    #pragma unroll 1
    for (int t = 0; t < NSTEPS; ++t) {
        const __half* hi = (t & 1) ? g_hB : g_hA;
        __half* ho       = (t & 1) ? g_hA : g_hB;
        const __half* xp;
        int xstride;
        if (t < TIN) { xp = g_in + (size_t)t * FDIM; xstride = TIN * FDIM; }
        else         { xp = g_xd; xstride = FDIM; }

        auto issueA = [&](int c, int st) {
            const int nsub = (c == 8) ? 1 : 2;
            for (int s = 0; s < nsub; ++s) {
                const __half* ap;
                int lda;
                if (c < 8) { ap = hi + (size_t)m0 * UNITS + c * 128 + s * 64; lda = UNITS; }
                else       { ap = xp + (size_t)m0 * xstride;                  lda = xstride; }
                const uint32_t sb = sbase + SM_STG + st * STAGE_B + s * A_SUB_B;
                #pragma unroll
                for (int i = 0; i < 4; ++i) {
                    const int idx = i * 128 + tid;
                    const int row = idx >> 3, ch = idx & 7;
                    cp16(sb + SWZ(row * 128 + ch * 16), ap + (size_t)row * lda + ch * 8);
                }
            }
        };

        int c0;
        if (t == 0) { c0 = 8; issueA(8, 0); issueW(8, 0); cp_commit(); }  // h=0: x chunk only
        else        { c0 = 0; issueA(0, 0); cp_commit(); }                // W0 pre-issued last step

        #pragma unroll
        for (int i = 0; i < 2; ++i)
            #pragma unroll
            for (int j = 0; j < 8; ++j)
                #pragma unroll
                for (int r = 0; r < 4; ++r) acc[i][j][r] = 0.f;

        #pragma unroll 1
        for (int c = c0; c < NCHUNK; ++c) {
            const int st = c & 1;
            cp_wait<0>();
            __syncthreads();
            if (c + 1 < NCHUNK) { issueA(c + 1, st ^ 1); issueW(c + 1, st ^ 1); cp_commit(); }

            const uint32_t stg = sbase + SM_STG + st * STAGE_B;
            const int nk = (c == 8) ? 4 : 8;
            #pragma unroll 4
            for (int k16 = 0; k16 < nk; ++k16) {
                const int sub = k16 >> 2, kb = (k16 & 3) * 32;
                uint32_t ah[2][4], bh[4][4];
                #pragma unroll
                for (int mf = 0; mf < 2; ++mf)
                    ldm4(ah[mf], stg + sub * A_SUB_B + SWZ((a_r + mf * 16) * 128 + kb + a_cs));
                #pragma unroll
                for (int p = 0; p < 4; ++p)
                    ldm4(bh[p], stg + A_TILE_B + sub * B_SUB_B + SWZ((b_r + p * 16) * 128 + kb + b_cs));
                #pragma unroll
                for (int mf = 0; mf < 2; ++mf)
                    #pragma unroll
                    for (int nf = 0; nf < 8; ++nf)
                        mma16816(acc[mf][nf], ah[mf], &bh[nf >> 1][(nf & 1) * 2]);
            }
        }

        // ---- epilogue: z scratch overlays stage 1 (last chunk c=8 computed from stage 0) ----
        float* zs = (float*)(smem + SM_ZS);
        __syncthreads();
        {
            const int gr = lane >> 2, gcn = (lane & 3) * 2;
            #pragma unroll
            for (int mf = 0; mf < 2; ++mf)
                #pragma unroll
                for (int nf = 0; nf < 8; ++nf) {
                    const int row = warp_m * 32 + mf * 16 + gr;
                    const int col = warp_n * 64 + nf * 8 + gcn;
                    *(float2*)&zs[row * 132 + col]       = make_float2(acc[mf][nf][0], acc[mf][nf][1]);
                    *(float2*)&zs[(row + 8) * 132 + col] = make_float2(acc[mf][nf][2], acc[mf][nf][3]);
                }
        }
        __syncthreads();
        {
            const int m  = tid >> 1;            // 0..63
            const int ub = (tid & 1) * 16;      // local unit base: 0 or 16
            const float4* zrow  = (const float4*)&zs[m * 132];
            const float4* bias4 = (const float4*)smem;
            const size_t idx0 = (size_t)(m0 + m) * UNITS + u0 + ub;
            __align__(16) float hfv[16];
            __align__(16) __half hh[16];
            #pragma unroll
            for (int j = 0; j < 16; ++j) {
                const int ul = ub + j;
                const float4 z4 = zrow[ul];
                const float4 bb = bias4[ul];
                const float zi = z4.x + bb.x;
                const float zf = z4.y + bb.y;
                const float zg = z4.z + bb.z;
                const float zo = z4.w + bb.w;
                const float cn = sigm(zf) * cf[j] + sigm(zi) * ftanh(zg);
                cf[j] = cn;
                const float h = sigm(zo) * ftanh(cn);
                hfv[j] = h;
                hh[j] = __float2half(h);
            }
            *(uint4*)(ho + idx0)     = *(const uint4*)&hh[0];
            *(uint4*)(ho + idx0 + 8) = *(const uint4*)&hh[8];
            if (t >= TIN - 1) {   // fp32 h needed only by the dense head
                #pragma unroll
                for (int q = 0; q < 4; ++q)
                    *(float4*)(g_hf32 + idx0 + q * 4) = *(const float4*)&hfv[q * 4];
            }
        }

        if (t + 1 < NSTEPS) { issueW(0, 0); cp_commit(); }   // prefetch next step's W0 across the barrier
        grid_barrier(bx, ++lgen);

        if (t >= TIN - 1) {
            const int ds = t - (TIN - 1);
            if (flat < 64) {
                const int bg = flat >> 3;
                const int fg = flat & 7;
                const int bl_ = tid >> 1;                 // 0..63
                const int f0 = fg * 8 + (tid & 1) * 4;    // 4 features per thread
                const int b  = bg * 64 + bl_;
                const float4* hp = (const float4*)(g_hf32 + (size_t)b * UNITS);
                float a0 = 0.f, a1 = 0.f, a2 = 0.f, a3 = 0.f;
                #pragma unroll 4
                for (int kq = 0; kq < UNITS / 4; ++kq) {
                    const float4 hv = __ldcg(hp + kq);
                    const float* w = Wd + (size_t)kq * 4 * FDIM;
                    a0 = fmaf(hv.x, w[f0 + 0], a0);
                    a0 = fmaf(hv.y, w[64 + f0 + 0], a0);
                    a0 = fmaf(hv.z, w[128 + f0 + 0], a0);
                    a0 = fmaf(hv.w, w[192 + f0 + 0], a0);
                    a1 = fmaf(hv.x, w[f0 + 1], a1);
                    a1 = fmaf(hv.y, w[64 + f0 + 1], a1);
                    a1 = fmaf(hv.z, w[128 + f0 + 1], a1);
                    a1 = fmaf(hv.w, w[192 + f0 + 1], a1);
                    a2 = fmaf(hv.x, w[f0 + 2], a2);
                    a2 = fmaf(hv.y, w[64 + f0 + 2], a2);
                    a2 = fmaf(hv.z, w[128 + f0 + 2], a2);
                    a2 = fmaf(hv.w, w[192 + f0 + 2], a2);
                    a3 = fmaf(hv.x, w[f0 + 3], a3);
                    a3 = fmaf(hv.y, w[64 + f0 + 3], a3);
                    a3 = fmaf(hv.z, w[128 + f0 + 3], a3);
                    a3 = fmaf(hv.w, w[192 + f0 + 3], a3);
                }
                const float p0 = a0 + bd[f0 + 0];
                const float p1 = a1 + bd[f0 + 1];
                const float p2 = a2 + bd[f0 + 2];
                const float p3 = a3 + bd[f0 + 3];
                float* op = out + (size_t)b * (OUT_STEPS * FDIM) + (size_t)ds * FDIM + f0;
                op[0] = p0; op[1] = p1; op[2] = p2; op[3] = p3;
                __half* xo = g_xd + (size_t)b * FDIM + f0;
                xo[0] = __float2half(p0);
                xo[1] = __float2half(p1);
                xo[2] = __float2half(p2);
                xo[3] = __float2half(p3);
            }
            if (t + 1 < NSTEPS) grid_barrier(bx, ++lgen);
        }
    }
}

// ---------------- preprocessing: coalesced tiled transpose to fp16 ----------------
__global__ __launch_bounds__(256)
void prep_weights(const float* __restrict__ Wk, const float* __restrict__ Wr,
                  const float* __restrict__ b) {
    __shared__ float tile[64][65];            // [n'_loc][k_loc]
    const int k0 = blockIdx.x * 64;
    const int u0 = blockIdx.y * 16;
    const int r  = threadIdx.x >> 2;
    const int cq = threadIdx.x & 3;
    const int k  = k0 + r;
    #pragma unroll
    for (int g = 0; g < 4; ++g) {
        const int col = g * UNITS + u0 + cq * 4;
        float4 v;
        if (k < UNITS) v = *(const float4*)(Wr + (size_t)k * NGATE + col);
        else           v = *(const float4*)(Wk + (size_t)(k - UNITS) * NGATE + col);
        tile[(cq * 4 + 0) * 4 + g][r] = v.x;
        tile[(cq * 4 + 1) * 4 + g][r] = v.y;
        tile[(cq * 4 + 2) * 4 + g][r] = v.z;
        tile[(cq * 4 + 3) * 4 + g][r] = v.w;
    }
    if (blockIdx.x == 0 && blockIdx.y == 0)
        for (int i = threadIdx.x; i < NGATE; i += 256)
            g_b2[i] = b[(i & 3) * UNITS + (i >> 2)];
    __syncthreads();
    const int nl = threadIdx.x >> 2;
    const int kk = (threadIdx.x & 3) * 16;
    const size_t ng = (size_t)(blockIdx.y * 64 + nl);
    __align__(16) __half hb[16];
    #pragma unroll
    for (int j = 0; j < 16; ++j)
        hb[j] = __float2half(tile[nl][kk + j]);
    *(uint4*)(g_Wt + ng * KTOT + k0 + kk)     = *(const uint4*)&hb[0];
    *(uint4*)(g_Wt + ng * KTOT + k0 + kk + 8) = *(const uint4*)&hb[8];
}

__global__ void prep_inputs(const float* __restrict__ inp) {
    const size_t idx = (size_t)blockIdx.x * blockDim.x + threadIdx.x;
    if (idx < (size_t)BSZ * TIN * FDIM)
        g_in[idx] = __float2half(inp[idx]);
}

// ---------------- launch ----------------
extern "C" void kernel_launch(void* const* d_in, const int* in_sizes, int n_in,
                              void* d_out, int out_size)
{
    const float* inputs = (const float*)d_in[0];
    const float* Wk     = (const float*)d_in[1];
    const float* Wr     = (const float*)d_in[2];
    const float* bias   = (const float*)d_in[3];
    const float* Wd     = (const float*)d_in[4];
    const float* bd     = (const float*)d_in[5];
    float* out = (float*)d_out;

    static bool attr_done = false;
    if (!attr_done) {
        cudaFuncSetAttribute(lstm_persist, cudaFuncAttributeMaxDynamicSharedMemorySize, SM_TOTAL);
        attr_done = true;
    }

    void* bar1_addr; void* bar2_addr;
    cudaGetSymbolAddress(&bar1_addr, g_bar1);
    cudaGetSymbolAddress(&bar2_addr, g_bar2);
    cudaMemsetAsync(bar1_addr, 0, 8 * 32 * sizeof(unsigned));
    cudaMemsetAsync(bar2_addr, 0, 32 * sizeof(unsigned));

    prep_weights<<<dim3(17, 64), 256>>>(Wk, Wr, bias);
    {
        const size_t ni = (size_t)BSZ * TIN * FDIM;
        prep_inputs<<<(unsigned)((ni + 255) / 256), 256>>>(inputs);
    }

    lstm_persist<<<dim3(BSZ / 64, NGATE / 128), 128, SM_TOTAL>>>(Wd, bd, out);
}

// round 15
// speedup vs baseline: 1.1034x; 1.1034x over previous
#include <cuda_runtime.h>
#include <cuda_fp16.h>
#include <stdint.h>
#include <math.h>

#define BSZ 512
#define TIN 128
#define FDIM 64
#define UNITS 1024
#define OUT_STEPS 32
#define NSTEPS 159           // TIN + OUT_STEPS - 1 LSTM steps
#define NGATE 4096           // 4*UNITS, gate-interleaved: n' = u*4 + g
#define KTOT 1088            // 1024 (h) + 64 (x)
#define NCHUNK 9             // 8 h-chunks (K=128 each) + 1 x half-chunk (K=64)
#define NBLK 256

// ---------------- persistent device scratch (allocation-free) ----------------
__device__ __half g_Wt[(size_t)NGATE * KTOT];     // fp16 weights, [n'][k] K-major
__device__ float  g_b2[NGATE];                    // bias reordered to n'
__device__ __half g_in[(size_t)BSZ * TIN * FDIM]; // fp16 inputs
__device__ __half g_hA[(size_t)BSZ * UNITS];
__device__ __half g_hB[(size_t)BSZ * UNITS];
__device__ __half g_xd[(size_t)BSZ * FDIM];       // decode input = fp16(pred)
__device__ unsigned g_bar1[8 * 32];               // level-1 counters (1/batch lane, 128B apart)
__device__ unsigned g_bar2[32];                   // [0]=root count, [16]=generation
__device__ int    g_xflag;                        // #dense-CTA completions (monotonic)

__device__ __forceinline__ uint32_t smem_u32(const void* p) {
    uint32_t a;
    asm("{ .reg .u64 t; cvta.to.shared.u64 t, %1; cvt.u32.u64 %0, t; }" : "=r"(a) : "l"(p));
    return a;
}
__device__ __forceinline__ void cp16(uint32_t saddr, const void* g) {
    asm volatile("cp.async.cg.shared.global [%0], [%1], 16;" :: "r"(saddr), "l"(g));
}
__device__ __forceinline__ void cp_commit() {
    asm volatile("cp.async.commit_group;" ::: "memory");
}
template <int N>
__device__ __forceinline__ void cp_wait() {
    asm volatile("cp.async.wait_group %0;" :: "n"(N) : "memory");
}
__device__ __forceinline__ void ldm4(uint32_t* r, uint32_t addr) {
    asm volatile("ldmatrix.sync.aligned.m8n8.x4.shared.b16 {%0,%1,%2,%3}, [%4];"
        : "=r"(r[0]), "=r"(r[1]), "=r"(r[2]), "=r"(r[3]) : "r"(addr));
}
// mma.sync m16n8k16 row.col fp16 -> f32 (baseline PTX)
__device__ __forceinline__ void mma16816(float* d, const uint32_t* a, const uint32_t* b) {
    asm volatile(
        "mma.sync.aligned.m16n8k16.row.col.f32.f16.f16.f32 "
        "{%0,%1,%2,%3}, {%4,%5,%6,%7}, {%8,%9}, {%0,%1,%2,%3};"
        : "+f"(d[0]), "+f"(d[1]), "+f"(d[2]), "+f"(d[3])
        : "r"(a[0]), "r"(a[1]), "r"(a[2]), "r"(a[3]), "r"(b[0]), "r"(b[1]));
}
__device__ __forceinline__ float sigm(float x) {
    return __fdividef(1.0f, 1.0f + __expf(-x));
}
__device__ __forceinline__ float ftanh(float x) {
    return __fdividef(2.0f, 1.0f + __expf(-2.0f * x)) - 1.0f;
}

#define SWZ(o) ((o) ^ (((o) >> 3) & 0x70))

// ---------------- SMEM layout ----------------
// [0,512): bias (128 floats).
// Stage (48 KB): A = 2 subs of 8K (64 rows x 128B) @0, @8192;
//                B = 2 subs of 16K (128 rows x 128B) @16384, @32768.
// Two stages. Chunk c -> stage c&1 (last chunk c=8 -> stage 0).
// z scratch (64x132 f32 = 33792 B) overlays stage 1.
#define A_SUB_B 8192
#define A_TILE_B 16384
#define B_SUB_B 16384
#define STAGE_B 49152
#define SM_STG 512
#define SM_ZS (SM_STG + STAGE_B)
#define SM_TOTAL (SM_STG + 2 * STAGE_B)   // 98816 (2 CTAs/SM: 197KB < 228KB)

// Two-level barrier: 32 arrivals per batch-lane counter, then 8 on the root.
__device__ __forceinline__ void grid_barrier(int bx, unsigned target) {
    __threadfence();
    __syncthreads();
    if (threadIdx.x == 0) {
        if (atomicAdd(&g_bar1[bx * 32], 1u) == 31u) {
            atomicExch(&g_bar1[bx * 32], 0u);
            if (atomicAdd(&g_bar2[0], 1u) == 7u) {
                atomicExch(&g_bar2[0], 0u);
                __threadfence();
                atomicExch(&g_bar2[16], target);
            }
        }
        while (((volatile unsigned*)g_bar2)[16] < target) __nanosleep(32);
        __threadfence();
    }
    __syncthreads();
}

__global__ __launch_bounds__(256, 2)
void lstm_persist(const float* __restrict__ Wd,
                  const float* __restrict__ bd,
                  float* __restrict__ out)
{
    extern __shared__ char smem[];
    const uint32_t sbase = smem_u32(smem);
    const int tid = threadIdx.x, wid = tid >> 5, lane = tid & 31;
    const int warp_m = wid >> 2;            // 0..1 -> rows warp_m*32
    const int warp_n = wid & 3;             // 0..3 -> cols warp_n*32
    const int bx = blockIdx.x;
    const int m0 = bx * 64;                 // batch tile (M=64)
    const int n0 = blockIdx.y * 128;        // gate-interleaved column base (N=128)
    const int u0 = blockIdx.y * 32;
    const int flat = blockIdx.y * gridDim.x + bx;

    if (tid < 128) ((float*)smem)[tid] = g_b2[n0 + tid];

    const __half* __restrict__ Bw = g_Wt + (size_t)n0 * KTOT;

    const int a_r  = warp_m * 32 + (lane & 15);
    const int a_cs = (lane >> 4) * 16;
    const int b_r  = warp_n * 32 + (lane & 7) + ((lane >> 4) << 3);
    const int b_cs = ((lane >> 3) & 1) * 16;

    unsigned lgen = 0;

    // persistent cell state: this (CTA, thread) owns the same 8 units forever
    float cf[8];
    #pragma unroll
    for (int j = 0; j < 8; ++j) cf[j] = 0.f;

    float acc[2][4][4];

    // W loader: chunk c covers k = c*128 + sub*64 (c=8: one sub only, k=1024..1087)
    auto issueW = [&](int c, int st) {
        const int nsub = (c == 8) ? 1 : 2;
        for (int s = 0; s < nsub; ++s) {
            const uint32_t sb = sbase + SM_STG + st * STAGE_B + A_TILE_B + s * B_SUB_B;
            const __half* wp = Bw + (size_t)(c * 128 + s * 64);
            #pragma unroll
            for (int i = 0; i < 4; ++i) {
                const int idx = i * 256 + tid;
                const int row = idx >> 3, ch = idx & 7;
                cp16(sb + SWZ(row * 128 + ch * 16), wp + (size_t)row * KTOT + ch * 8);
            }
        }
    };

    #pragma unroll 1
    for (int t = 0; t < NSTEPS; ++t) {
        const __half* hi = (t & 1) ? g_hB : g_hA;
        __half* ho       = (t & 1) ? g_hA : g_hB;
        const __half* xp;
        int xstride;
        if (t < TIN) { xp = g_in + (size_t)t * FDIM; xstride = TIN * FDIM; }
        else         { xp = g_xd; xstride = FDIM; }

        auto issueA = [&](int c, int st) {
            const int nsub = (c == 8) ? 1 : 2;
            for (int s = 0; s < nsub; ++s) {
                const __half* ap;
                int lda;
                if (c < 8) { ap = hi + (size_t)m0 * UNITS + c * 128 + s * 64; lda = UNITS; }
                else       { ap = xp + (size_t)m0 * xstride;                  lda = xstride; }
                const uint32_t sb = sbase + SM_STG + st * STAGE_B + s * A_SUB_B;
                #pragma unroll
                for (int i = 0; i < 2; ++i) {
                    const int idx = i * 256 + tid;
                    const int row = idx >> 3, ch = idx & 7;
                    cp16(sb + SWZ(row * 128 + ch * 16), ap + (size_t)row * lda + ch * 8);
                }
            }
        };

        int c0;
        if (t == 0) { c0 = 8; issueA(8, 0); issueW(8, 0); cp_commit(); }  // h=0: x chunk only
        else        { c0 = 0; issueA(0, 0); cp_commit(); }                // W0 pre-issued last step

        #pragma unroll
        for (int i = 0; i < 2; ++i)
            #pragma unroll
            for (int j = 0; j < 4; ++j)
                #pragma unroll
                for (int r = 0; r < 4; ++r) acc[i][j][r] = 0.f;

        #pragma unroll 1
        for (int c = c0; c < NCHUNK; ++c) {
            const int st = c & 1;
            cp_wait<0>();
            __syncthreads();
            if (c + 1 < NCHUNK) {
                if (c + 1 == 8 && t >= TIN) {
                    // x tile = dense outputs of step t-1; wait for all 256 dense CTAs
                    const int tgt = NBLK * (t - TIN);
                    volatile const int* vp = (volatile const int*)&g_xflag;
                    while (*vp < tgt) __nanosleep(32);
                    __threadfence();
                }
                issueA(c + 1, st ^ 1);
                issueW(c + 1, st ^ 1);
                cp_commit();
            }

            const uint32_t stg = sbase + SM_STG + st * STAGE_B;
            const int nk = (c == 8) ? 4 : 8;
            #pragma unroll 4
            for (int k16 = 0; k16 < nk; ++k16) {
                const int sub = k16 >> 2, kb = (k16 & 3) * 32;
                uint32_t ah[2][4], bh[2][4];
                #pragma unroll
                for (int mf = 0; mf < 2; ++mf)
                    ldm4(ah[mf], stg + sub * A_SUB_B + SWZ((a_r + mf * 16) * 128 + kb + a_cs));
                #pragma unroll
                for (int p = 0; p < 2; ++p)
                    ldm4(bh[p], stg + A_TILE_B + sub * B_SUB_B + SWZ((b_r + p * 16) * 128 + kb + b_cs));
                #pragma unroll
                for (int mf = 0; mf < 2; ++mf)
                    #pragma unroll
                    for (int nf = 0; nf < 4; ++nf)
                        mma16816(acc[mf][nf], ah[mf], &bh[nf >> 1][(nf & 1) * 2]);
            }
        }

        // ---- epilogue: z scratch overlays stage 1 (last chunk c=8 computed from stage 0) ----
        float* zs = (float*)(smem + SM_ZS);
        __syncthreads();
        {
            const int gr = lane >> 2, gcn = (lane & 3) * 2;
            #pragma unroll
            for (int mf = 0; mf < 2; ++mf)
                #pragma unroll
                for (int nf = 0; nf < 4; ++nf) {
                    const int row = warp_m * 32 + mf * 16 + gr;
                    const int col = warp_n * 32 + nf * 8 + gcn;
                    *(float2*)&zs[row * 132 + col]       = make_float2(acc[mf][nf][0], acc[mf][nf][1]);
                    *(float2*)&zs[(row + 8) * 132 + col] = make_float2(acc[mf][nf][2], acc[mf][nf][3]);
                }
        }
        __syncthreads();
        {
            const int m  = tid >> 2;
            const int ub = (tid & 3) * 8;
            const float4* zrow  = (const float4*)&zs[m * 132];
            const float4* bias4 = (const float4*)smem;
            const size_t idx0 = (size_t)(m0 + m) * UNITS + u0 + ub;
            __align__(8) __half hh[8];
            #pragma unroll
            for (int j = 0; j < 8; ++j) {
                const int ul = ub + j;
                const float4 z4 = zrow[ul];
                const float4 bb = bias4[ul];
                const float zi = z4.x + bb.x;
                const float zf = z4.y + bb.y;
                const float zg = z4.z + bb.z;
                const float zo = z4.w + bb.w;
                const float cn = sigm(zf) * cf[j] + sigm(zi) * ftanh(zg);
                cf[j] = cn;
                const float h = sigm(zo) * ftanh(cn);
                hh[j] = __float2half(h);
            }
            *(uint4*)(ho + idx0) = *(const uint4*)&hh[0];
        }

        if (t + 1 < NSTEPS) { issueW(0, 0); cp_commit(); }   // prefetch next step's W0 across the barrier
        grid_barrier(bx, ++lgen);

        // ---- dense head: ALL CTAs, 2 batches x 64 features each (~1.5us, uniform) ----
        if (t >= TIN - 1) {
            const int ds = t - (TIN - 1);
            if (tid < 128) {
                const int b = flat * 2 + (tid >> 6);
                const int f = tid & 63;
                const uint2* hp = (const uint2*)(ho + (size_t)b * UNITS);
                float a0 = 0.f;
                #pragma unroll 4
                for (int kq = 0; kq < UNITS / 4; ++kq) {
                    const uint2 hv = __ldcg(hp + kq);
                    const float2 h01 = __half22float2(*reinterpret_cast<const __half2*>(&hv.x));
                    const float2 h23 = __half22float2(*reinterpret_cast<const __half2*>(&hv.y));
                    const float* w = Wd + (size_t)kq * 4 * FDIM;
                    a0 = fmaf(h01.x, w[f], a0);
                    a0 = fmaf(h01.y, w[64 + f], a0);
                    a0 = fmaf(h23.x, w[128 + f], a0);
                    a0 = fmaf(h23.y, w[192 + f], a0);
                }
                const float p = a0 + bd[f];
                out[(size_t)b * (OUT_STEPS * FDIM) + (size_t)ds * FDIM + f] = p;
                g_xd[(size_t)b * FDIM + f] = __float2half(p);
            }
            __syncthreads();
            __threadfence();
            if (tid == 0) atomicAdd(&g_xflag, 1);
        }
    }
}

// ---------------- preprocessing: coalesced tiled transpose to fp16 ----------------
__global__ __launch_bounds__(256)
void prep_weights(const float* __restrict__ Wk, const float* __restrict__ Wr,
                  const float* __restrict__ b) {
    __shared__ float tile[64][65];            // [n'_loc][k_loc]
    const int k0 = blockIdx.x * 64;
    const int u0 = blockIdx.y * 16;
    const int r  = threadIdx.x >> 2;
    const int cq = threadIdx.x & 3;
    const int k  = k0 + r;
    #pragma unroll
    for (int g = 0; g < 4; ++g) {
        const int col = g * UNITS + u0 + cq * 4;
        float4 v;
        if (k < UNITS) v = *(const float4*)(Wr + (size_t)k * NGATE + col);
        else           v = *(const float4*)(Wk + (size_t)(k - UNITS) * NGATE + col);
        tile[(cq * 4 + 0) * 4 + g][r] = v.x;
        tile[(cq * 4 + 1) * 4 + g][r] = v.y;
        tile[(cq * 4 + 2) * 4 + g][r] = v.z;
        tile[(cq * 4 + 3) * 4 + g][r] = v.w;
    }
    if (blockIdx.x == 0 && blockIdx.y == 0)
        for (int i = threadIdx.x; i < NGATE; i += 256)
            g_b2[i] = b[(i & 3) * UNITS + (i >> 2)];
    __syncthreads();
    const int nl = threadIdx.x >> 2;
    const int kk = (threadIdx.x & 3) * 16;
    const size_t ng = (size_t)(blockIdx.y * 64 + nl);
    __align__(16) __half hb[16];
    #pragma unroll
    for (int j = 0; j < 16; ++j)
        hb[j] = __float2half(tile[nl][kk + j]);
    *(uint4*)(g_Wt + ng * KTOT + k0 + kk)     = *(const uint4*)&hb[0];
    *(uint4*)(g_Wt + ng * KTOT + k0 + kk + 8) = *(const uint4*)&hb[8];
}

__global__ void prep_inputs(const float* __restrict__ inp) {
    const size_t idx = (size_t)blockIdx.x * blockDim.x + threadIdx.x;
    if (idx < (size_t)BSZ * TIN * FDIM)
        g_in[idx] = __float2half(inp[idx]);
}

// ---------------- launch ----------------
extern "C" void kernel_launch(void* const* d_in, const int* in_sizes, int n_in,
                              void* d_out, int out_size)
{
    const float* inputs = (const float*)d_in[0];
    const float* Wk     = (const float*)d_in[1];
    const float* Wr     = (const float*)d_in[2];
    const float* bias   = (const float*)d_in[3];
    const float* Wd     = (const float*)d_in[4];
    const float* bd     = (const float*)d_in[5];
    float* out = (float*)d_out;

    static bool attr_done = false;
    if (!attr_done) {
        cudaFuncSetAttribute(lstm_persist, cudaFuncAttributeMaxDynamicSharedMemorySize, SM_TOTAL);
        attr_done = true;
    }

    void* bar1_addr; void* bar2_addr; void* xflag_addr;
    cudaGetSymbolAddress(&bar1_addr, g_bar1);
    cudaGetSymbolAddress(&bar2_addr, g_bar2);
    cudaGetSymbolAddress(&xflag_addr, g_xflag);
    cudaMemsetAsync(bar1_addr, 0, 8 * 32 * sizeof(unsigned));
    cudaMemsetAsync(bar2_addr, 0, 32 * sizeof(unsigned));
    cudaMemsetAsync(xflag_addr, 0, sizeof(int));

    prep_weights<<<dim3(17, 64), 256>>>(Wk, Wr, bias);
    {
        const size_t ni = (size_t)BSZ * TIN * FDIM;
        prep_inputs<<<(unsigned)((ni + 255) / 256), 256>>>(inputs);
    }

    lstm_persist<<<dim3(BSZ / 64, NGATE / 128), 256, SM_TOTAL>>>(Wd, bd, out);
}

// round 16
// speedup vs baseline: 1.1075x; 1.0037x over previous
#include <cuda_runtime.h>
#include <cuda_fp16.h>
#include <stdint.h>
#include <math.h>

#define BSZ 512
#define TIN 128
#define FDIM 64
#define UNITS 1024
#define OUT_STEPS 32
#define NSTEPS 159           // TIN + OUT_STEPS - 1 LSTM steps
#define NGATE 4096           // 4*UNITS, gate-interleaved: n' = u*4 + g
#define KTOT 1088            // 1024 (h) + 64 (x)
#define NCHUNK 17            // 16 h-chunks (K=64) + 1 x chunk (K=64)
#define NBLK 128             // 4 batch lanes x 32 unit groups

// ---------------- persistent device scratch (allocation-free) ----------------
__device__ __half g_Wt[(size_t)NGATE * KTOT];     // fp16 weights, [n'][k] K-major
__device__ float  g_b2[NGATE];                    // bias reordered to n'
__device__ __half g_in[(size_t)BSZ * TIN * FDIM]; // fp16 inputs
__device__ __half g_hA[(size_t)BSZ * UNITS];
__device__ __half g_hB[(size_t)BSZ * UNITS];
__device__ __half g_xd[(size_t)BSZ * FDIM];       // decode input = fp16(pred)
__device__ unsigned g_bar1[4 * 32];               // level-1 counters (1/batch lane, 128B apart)
__device__ unsigned g_bar2[32];                   // [0]=root count, [16]=generation
__device__ int    g_xflag;                        // #dense-CTA completions (monotonic)

__device__ __forceinline__ uint32_t smem_u32(const void* p) {
    uint32_t a;
    asm("{ .reg .u64 t; cvta.to.shared.u64 t, %1; cvt.u32.u64 %0, t; }" : "=r"(a) : "l"(p));
    return a;
}
__device__ __forceinline__ void cp16(uint32_t saddr, const void* g) {
    asm volatile("cp.async.cg.shared.global [%0], [%1], 16;" :: "r"(saddr), "l"(g));
}
__device__ __forceinline__ void cp_commit() {
    asm volatile("cp.async.commit_group;" ::: "memory");
}
template <int N>
__device__ __forceinline__ void cp_wait() {
    asm volatile("cp.async.wait_group %0;" :: "n"(N) : "memory");
}
__device__ __forceinline__ void ldm4(uint32_t* r, uint32_t addr) {
    asm volatile("ldmatrix.sync.aligned.m8n8.x4.shared.b16 {%0,%1,%2,%3}, [%4];"
        : "=r"(r[0]), "=r"(r[1]), "=r"(r[2]), "=r"(r[3]) : "r"(addr));
}
// mma.sync m16n8k16 row.col fp16 -> f32 (baseline PTX)
__device__ __forceinline__ void mma16816(float* d, const uint32_t* a, const uint32_t* b) {
    asm volatile(
        "mma.sync.aligned.m16n8k16.row.col.f32.f16.f16.f32 "
        "{%0,%1,%2,%3}, {%4,%5,%6,%7}, {%8,%9}, {%0,%1,%2,%3};"
        : "+f"(d[0]), "+f"(d[1]), "+f"(d[2]), "+f"(d[3])
        : "r"(a[0]), "r"(a[1]), "r"(a[2]), "r"(a[3]), "r"(b[0]), "r"(b[1]));
}
__device__ __forceinline__ float sigm(float x) {
    return __fdividef(1.0f, 1.0f + __expf(-x));
}
__device__ __forceinline__ float ftanh(float x) {
    return __fdividef(2.0f, 1.0f + __expf(-2.0f * x)) - 1.0f;
}

#define SWZ(o) ((o) ^ (((o) >> 3) & 0x70))

// ---------------- SMEM layout ----------------
// [0,512): bias (128 floats).
// Stage (32 KB): A = 128 rows x 128B = 16K @0; B = 128 rows x 128B = 16K @16384.
// Two stages @512, @33280. Chunk c -> stage c&1 (last chunk c=16 -> stage 0).
// z scratch (128 x 132 f32 = 67584 B) overlays stage 1.
#define A_TILE_B 16384
#define STAGE_B 32768
#define SM_STG 512
#define SM_ZS (SM_STG + STAGE_B)
#define SM_TOTAL (SM_ZS + 67584)          // 100864

// Two-level barrier: 32 arrivals per batch-lane counter, then 4 on the root.
__device__ __forceinline__ void grid_barrier(int bx, unsigned target) {
    __threadfence();
    __syncthreads();
    if (threadIdx.x == 0) {
        if (atomicAdd(&g_bar1[bx * 32], 1u) == 31u) {
            atomicExch(&g_bar1[bx * 32], 0u);
            if (atomicAdd(&g_bar2[0], 1u) == 3u) {
                atomicExch(&g_bar2[0], 0u);
                __threadfence();
                atomicExch(&g_bar2[16], target);
            }
        }
        while (((volatile unsigned*)g_bar2)[16] < target) __nanosleep(32);
        __threadfence();
    }
    __syncthreads();
}

__global__ __launch_bounds__(256, 1)
void lstm_persist(const float* __restrict__ Wd,
                  const float* __restrict__ bd,
                  float* __restrict__ out)
{
    extern __shared__ char smem[];
    const uint32_t sbase = smem_u32(smem);
    const int tid = threadIdx.x, wid = tid >> 5, lane = tid & 31;
    const int warp_m = wid >> 2;            // 0..1 -> rows warp_m*64
    const int warp_n = wid & 3;             // 0..3 -> cols warp_n*32
    const int bx = blockIdx.x;              // batch lane 0..3
    const int m0 = bx * 128;                // batch tile (M=128)
    const int n0 = blockIdx.y * 128;        // gate-interleaved column base (N=128)
    const int u0 = blockIdx.y * 32;
    const int flat = blockIdx.y * gridDim.x + bx;   // 0..127

    if (tid < 128) ((float*)smem)[tid] = g_b2[n0 + tid];

    const __half* __restrict__ Bw = g_Wt + (size_t)n0 * KTOT;

    const int a_r  = warp_m * 64 + (lane & 15);          // + mf*16, mf 0..3
    const int a_cs = (lane >> 4) * 16;
    const int b_r  = warp_n * 32 + (lane & 7) + ((lane >> 4) << 3);  // + p*16, p 0..1
    const int b_cs = ((lane >> 3) & 1) * 16;

    unsigned lgen = 0;

    // persistent cell state: this (CTA, thread) owns the same 16 units forever
    float cf[16];
    #pragma unroll
    for (int j = 0; j < 16; ++j) cf[j] = 0.f;

    float acc[4][4][4];   // warp tile 64x32: mf 0..3, nf 0..3

    // W loader: chunk c covers k = c*64 .. c*64+63 (c=16 -> k 1024..1087)
    auto issueW = [&](int c, int st) {
        const uint32_t sb = sbase + SM_STG + st * STAGE_B + A_TILE_B;
        const __half* wp = Bw + (size_t)(c * 64);
        #pragma unroll
        for (int i = 0; i < 4; ++i) {
            const int idx = i * 256 + tid;
            const int row = idx >> 3, ch = idx & 7;
            cp16(sb + SWZ(row * 128 + ch * 16), wp + (size_t)row * KTOT + ch * 8);
        }
    };

    #pragma unroll 1
    for (int t = 0; t < NSTEPS; ++t) {
        const __half* hi = (t & 1) ? g_hB : g_hA;
        __half* ho       = (t & 1) ? g_hA : g_hB;
        const __half* xp;
        int xstride;
        if (t < TIN) { xp = g_in + (size_t)t * FDIM; xstride = TIN * FDIM; }
        else         { xp = g_xd; xstride = FDIM; }

        auto issueA = [&](int c, int st) {
            const __half* ap;
            int lda;
            if (c < 16) { ap = hi + (size_t)m0 * UNITS + c * 64; lda = UNITS; }
            else        { ap = xp + (size_t)m0 * xstride;        lda = xstride; }
            const uint32_t sb = sbase + SM_STG + st * STAGE_B;
            #pragma unroll
            for (int i = 0; i < 4; ++i) {
                const int idx = i * 256 + tid;
                const int row = idx >> 3, ch = idx & 7;
                cp16(sb + SWZ(row * 128 + ch * 16), ap + (size_t)row * lda + ch * 8);
            }
        };

        int c0;
        if (t == 0) { c0 = 16; issueA(16, 0); issueW(16, 0); cp_commit(); }  // h=0: x chunk only
        else        { c0 = 0;  issueA(0, 0);  cp_commit(); }                 // W0 pre-issued last step

        #pragma unroll
        for (int i = 0; i < 4; ++i)
            #pragma unroll
            for (int j = 0; j < 4; ++j)
                #pragma unroll
                for (int r = 0; r < 4; ++r) acc[i][j][r] = 0.f;

        #pragma unroll 1
        for (int c = c0; c < NCHUNK; ++c) {
            const int st = (c == 16) ? 0 : (c & 1);
            cp_wait<0>();
            __syncthreads();
            if (c + 1 < NCHUNK) {
                const int cn = c + 1;
                const int stn = (cn == 16) ? 0 : (cn & 1);
                if (cn == 16 && t >= TIN) {
                    // x tile = dense outputs of step t-1; wait for all dense CTAs
                    const int tgt = NBLK * (t - TIN + 1);
                    volatile const int* vp = (volatile const int*)&g_xflag;
                    while (*vp < tgt) __nanosleep(32);
                    __threadfence();
                }
                issueA(cn, stn);
                issueW(cn, stn);
                cp_commit();
            }

            const uint32_t stg = sbase + SM_STG + st * STAGE_B;
            #pragma unroll
            for (int k16 = 0; k16 < 4; ++k16) {
                const int kb = k16 * 32;
                uint32_t ah[4][4], bh[2][4];
                #pragma unroll
                for (int mf = 0; mf < 4; ++mf)
                    ldm4(ah[mf], stg + SWZ((a_r + mf * 16) * 128 + kb + a_cs));
                #pragma unroll
                for (int p = 0; p < 2; ++p)
                    ldm4(bh[p], stg + A_TILE_B + SWZ((b_r + p * 16) * 128 + kb + b_cs));
                #pragma unroll
                for (int mf = 0; mf < 4; ++mf)
                    #pragma unroll
                    for (int nf = 0; nf < 4; ++nf)
                        mma16816(acc[mf][nf], ah[mf], &bh[nf >> 1][(nf & 1) * 2]);
            }
        }

        // ---- epilogue: z scratch overlays stage 1 (last chunk c=16 computed from stage 0) ----
        float* zs = (float*)(smem + SM_ZS);
        __syncthreads();
        {
            const int gr = lane >> 2, gcn = (lane & 3) * 2;
            #pragma unroll
            for (int mf = 0; mf < 4; ++mf)
                #pragma unroll
                for (int nf = 0; nf < 4; ++nf) {
                    const int row = warp_m * 64 + mf * 16 + gr;
                    const int col = warp_n * 32 + nf * 8 + gcn;
                    *(float2*)&zs[row * 132 + col]       = make_float2(acc[mf][nf][0], acc[mf][nf][1]);
                    *(float2*)&zs[(row + 8) * 132 + col] = make_float2(acc[mf][nf][2], acc[mf][nf][3]);
                }
        }
        __syncthreads();
        {
            const int m  = tid >> 1;            // 0..127
            const int ub = (tid & 1) * 16;      // local unit base: 0 or 16
            const float4* zrow  = (const float4*)&zs[m * 132];
            const float4* bias4 = (const float4*)smem;
            const size_t idx0 = (size_t)(m0 + m) * UNITS + u0 + ub;
            __align__(16) __half hh[16];
            #pragma unroll
            for (int j = 0; j < 16; ++j) {
                const int ul = ub + j;
                const float4 z4 = zrow[ul];
                const float4 bb = bias4[ul];
                const float zi = z4.x + bb.x;
                const float zf = z4.y + bb.y;
                const float zg = z4.z + bb.z;
                const float zo = z4.w + bb.w;
                const float cn = sigm(zf) * cf[j] + sigm(zi) * ftanh(zg);
                cf[j] = cn;
                const float h = sigm(zo) * ftanh(cn);
                hh[j] = __float2half(h);
            }
            *(uint4*)(ho + idx0)     = *(const uint4*)&hh[0];
            *(uint4*)(ho + idx0 + 8) = *(const uint4*)&hh[8];
        }

        if (t + 1 < NSTEPS) { issueW(0, 0); cp_commit(); }   // prefetch next step's W0 across the barrier
        grid_barrier(bx, ++lgen);

        // ---- dense head: ALL CTAs, 4 batches x 64 features each (~1.5us, uniform) ----
        if (t >= TIN - 1) {
            const int ds = t - (TIN - 1);
            const int b = flat * 4 + (tid >> 6);
            const int f = tid & 63;
            const uint2* hp = (const uint2*)(ho + (size_t)b * UNITS);
            float a0 = 0.f;
            #pragma unroll 4
            for (int kq = 0; kq < UNITS / 4; ++kq) {
                const uint2 hv = __ldcg(hp + kq);
                const float2 h01 = __half22float2(*reinterpret_cast<const __half2*>(&hv.x));
                const float2 h23 = __half22float2(*reinterpret_cast<const __half2*>(&hv.y));
                const float* w = Wd + (size_t)kq * 4 * FDIM;
                a0 = fmaf(h01.x, w[f], a0);
                a0 = fmaf(h01.y, w[64 + f], a0);
                a0 = fmaf(h23.x, w[128 + f], a0);
                a0 = fmaf(h23.y, w[192 + f], a0);
            }
            const float p = a0 + bd[f];
            out[(size_t)b * (OUT_STEPS * FDIM) + (size_t)ds * FDIM + f] = p;
            g_xd[(size_t)b * FDIM + f] = __float2half(p);
            __syncthreads();
            __threadfence();
            if (tid == 0) atomicAdd(&g_xflag, 1);
        }
    }
}

// ---------------- preprocessing: coalesced tiled transpose to fp16 ----------------
__global__ __launch_bounds__(256)
void prep_weights(const float* __restrict__ Wk, const float* __restrict__ Wr,
                  const float* __restrict__ b) {
    __shared__ float tile[64][65];            // [n'_loc][k_loc]
    const int k0 = blockIdx.x * 64;
    const int u0 = blockIdx.y * 16;
    const int r  = threadIdx.x >> 2;
    const int cq = threadIdx.x & 3;
    const int k  = k0 + r;
    #pragma unroll
    for (int g = 0; g < 4; ++g) {
        const int col = g * UNITS + u0 + cq * 4;
        float4 v;
        if (k < UNITS) v = *(const float4*)(Wr + (size_t)k * NGATE + col);
        else           v = *(const float4*)(Wk + (size_t)(k - UNITS) * NGATE + col);
        tile[(cq * 4 + 0) * 4 + g][r] = v.x;
        tile[(cq * 4 + 1) * 4 + g][r] = v.y;
        tile[(cq * 4 + 2) * 4 + g][r] = v.z;
        tile[(cq * 4 + 3) * 4 + g][r] = v.w;
    }
    if (blockIdx.x == 0 && blockIdx.y == 0)
        for (int i = threadIdx.x; i < NGATE; i += 256)
            g_b2[i] = b[(i & 3) * UNITS + (i >> 2)];
    __syncthreads();
    const int nl = threadIdx.x >> 2;
    const int kk = (threadIdx.x & 3) * 16;
    const size_t ng = (size_t)(blockIdx.y * 64 + nl);
    __align__(16) __half hb[16];
    #pragma unroll
    for (int j = 0; j < 16; ++j)
        hb[j] = __float2half(tile[nl][kk + j]);
    *(uint4*)(g_Wt + ng * KTOT + k0 + kk)     = *(const uint4*)&hb[0];
    *(uint4*)(g_Wt + ng * KTOT + k0 + kk + 8) = *(const uint4*)&hb[8];
}

__global__ void prep_inputs(const float* __restrict__ inp) {
    const size_t idx = (size_t)blockIdx.x * blockDim.x + threadIdx.x;
    if (idx < (size_t)BSZ * TIN * FDIM)
        g_in[idx] = __float2half(inp[idx]);
}

// ---------------- launch ----------------
extern "C" void kernel_launch(void* const* d_in, const int* in_sizes, int n_in,
                              void* d_out, int out_size)
{
    const float* inputs = (const float*)d_in[0];
    const float* Wk     = (const float*)d_in[1];
    const float* Wr     = (const float*)d_in[2];
    const float* bias   = (const float*)d_in[3];
    const float* Wd     = (const float*)d_in[4];
    const float* bd     = (const float*)d_in[5];
    float* out = (float*)d_out;

    static bool attr_done = false;
    if (!attr_done) {
        cudaFuncSetAttribute(lstm_persist, cudaFuncAttributeMaxDynamicSharedMemorySize, SM_TOTAL);
        attr_done = true;
    }

    void* bar1_addr; void* bar2_addr; void* xflag_addr;
    cudaGetSymbolAddress(&bar1_addr, g_bar1);
    cudaGetSymbolAddress(&bar2_addr, g_bar2);
    cudaGetSymbolAddress(&xflag_addr, g_xflag);
    cudaMemsetAsync(bar1_addr, 0, 4 * 32 * sizeof(unsigned));
    cudaMemsetAsync(bar2_addr, 0, 32 * sizeof(unsigned));
    cudaMemsetAsync(xflag_addr, 0, sizeof(int));

    prep_weights<<<dim3(17, 64), 256>>>(Wk, Wr, bias);
    {
        const size_t ni = (size_t)BSZ * TIN * FDIM;
        prep_inputs<<<(unsigned)((ni + 255) / 256), 256>>>(inputs);
    }

    lstm_persist<<<dim3(4, 32), 256, SM_TOTAL>>>(Wd, bd, out);
}

// round 17
// speedup vs baseline: 1.1155x; 1.0072x over previous
#include <cuda_runtime.h>
#include <cuda_fp16.h>
#include <stdint.h>
#include <math.h>

#define BSZ 512
#define TIN 128
#define FDIM 64
#define UNITS 1024
#define OUT_STEPS 32
#define NSTEPS 159           // TIN + OUT_STEPS - 1 LSTM steps
#define NGATE 4096           // 4*UNITS, gate-interleaved: n' = u*4 + g
#define KTOT 1088            // 1024 (h) + 64 (x)
#define NCHUNK 9             // 8 h-chunks (K=128) + 1 x chunk (K=64)
#define NBLK 128             // 4 batch lanes x 32 unit groups

// ---------------- persistent device scratch (allocation-free) ----------------
__device__ __half g_Wt[(size_t)NGATE * KTOT];     // fp16 weights, [n'][k] K-major
__device__ float  g_b2[NGATE];                    // bias reordered to n'
__device__ __half g_in[(size_t)BSZ * TIN * FDIM]; // fp16 inputs
__device__ __half g_hA[(size_t)BSZ * UNITS];
__device__ __half g_hB[(size_t)BSZ * UNITS];
__device__ __half g_xd[(size_t)BSZ * FDIM];       // decode input = fp16(pred)
__device__ unsigned g_bar1[4 * 32];               // level-1 counters (1/batch lane, 128B apart)
__device__ unsigned g_bar2[32];                   // [0]=root count, [16]=generation
__device__ int    g_xflag;                        // #dense-CTA completions (monotonic)

__device__ __forceinline__ uint32_t smem_u32(const void* p) {
    uint32_t a;
    asm("{ .reg .u64 t; cvta.to.shared.u64 t, %1; cvt.u32.u64 %0, t; }" : "=r"(a) : "l"(p));
    return a;
}
__device__ __forceinline__ void cp16(uint32_t saddr, const void* g) {
    asm volatile("cp.async.cg.shared.global [%0], [%1], 16;" :: "r"(saddr), "l"(g));
}
__device__ __forceinline__ void cp_commit() {
    asm volatile("cp.async.commit_group;" ::: "memory");
}
template <int N>
__device__ __forceinline__ void cp_wait() {
    asm volatile("cp.async.wait_group %0;" :: "n"(N) : "memory");
}
__device__ __forceinline__ void ldm4(uint32_t* r, uint32_t addr) {
    asm volatile("ldmatrix.sync.aligned.m8n8.x4.shared.b16 {%0,%1,%2,%3}, [%4];"
        : "=r"(r[0]), "=r"(r[1]), "=r"(r[2]), "=r"(r[3]) : "r"(addr));
}
// mma.sync m16n8k16 row.col fp16 -> f32 (baseline PTX)
__device__ __forceinline__ void mma16816(float* d, const uint32_t* a, const uint32_t* b) {
    asm volatile(
        "mma.sync.aligned.m16n8k16.row.col.f32.f16.f16.f32 "
        "{%0,%1,%2,%3}, {%4,%5,%6,%7}, {%8,%9}, {%0,%1,%2,%3};"
        : "+f"(d[0]), "+f"(d[1]), "+f"(d[2]), "+f"(d[3])
        : "r"(a[0]), "r"(a[1]), "r"(a[2]), "r"(a[3]), "r"(b[0]), "r"(b[1]));
}
__device__ __forceinline__ float sigm(float x) {
    return __fdividef(1.0f, 1.0f + __expf(-x));
}
__device__ __forceinline__ float ftanh(float x) {
    return __fdividef(2.0f, 1.0f + __expf(-2.0f * x)) - 1.0f;
}

#define SWZ(o) ((o) ^ (((o) >> 3) & 0x70))

// ---------------- SMEM layout ----------------
// [0,512): bias (128 floats).
// Stage (64 KB): A = 2 subs x 16K (128 rows x 128B) @0, @16384;
//                B = 2 subs x 16K @32768, @49152.
// Two stages. Chunk c -> stage c&1 (last chunk c=8 -> stage 0).
// z scratch (128 x 132 f32 = 67584 B) overlays stage 1.
#define A_SUB_B 16384
#define A_TILE_B 32768
#define B_SUB_B 16384
#define STAGE_B 65536
#define SM_STG 512
#define SM_ZS (SM_STG + STAGE_B)
#define SM_TOTAL (SM_ZS + 67584)          // 133632 (occ 1)

// Two-level barrier: 32 arrivals per batch-lane counter, then 4 on the root.
__device__ __forceinline__ void grid_barrier(int bx, unsigned target) {
    __threadfence();
    __syncthreads();
    if (threadIdx.x == 0) {
        if (atomicAdd(&g_bar1[bx * 32], 1u) == 31u) {
            atomicExch(&g_bar1[bx * 32], 0u);
            if (atomicAdd(&g_bar2[0], 1u) == 3u) {
                atomicExch(&g_bar2[0], 0u);
                __threadfence();
                atomicExch(&g_bar2[16], target);
            }
        }
        while (((volatile unsigned*)g_bar2)[16] < target) __nanosleep(32);
        __threadfence();
    }
    __syncthreads();
}

__global__ __launch_bounds__(256, 1)
void lstm_persist(const float* __restrict__ Wd,
                  const float* __restrict__ bd,
                  float* __restrict__ out)
{
    extern __shared__ char smem[];
    const uint32_t sbase = smem_u32(smem);
    const int tid = threadIdx.x, wid = tid >> 5, lane = tid & 31;
    const int warp_m = wid >> 2;            // 0..1 -> rows warp_m*64
    const int warp_n = wid & 3;             // 0..3 -> cols warp_n*32
    const int bx = blockIdx.x;              // batch lane 0..3
    const int m0 = bx * 128;                // batch tile (M=128)
    const int n0 = blockIdx.y * 128;        // gate-interleaved column base (N=128)
    const int u0 = blockIdx.y * 32;
    const int flat = blockIdx.y * gridDim.x + bx;   // 0..127

    if (tid < 128) ((float*)smem)[tid] = g_b2[n0 + tid];

    const __half* __restrict__ Bw = g_Wt + (size_t)n0 * KTOT;

    const int a_r  = warp_m * 64 + (lane & 15);          // + mf*16, mf 0..3
    const int a_cs = (lane >> 4) * 16;
    const int b_r  = warp_n * 32 + (lane & 7) + ((lane >> 4) << 3);  // + p*16, p 0..1
    const int b_cs = ((lane >> 3) & 1) * 16;

    unsigned lgen = 0;

    // persistent cell state: this (CTA, thread) owns the same 16 units forever
    float cf[16];
    #pragma unroll
    for (int j = 0; j < 16; ++j) cf[j] = 0.f;

    float acc[4][4][4];   // warp tile 64x32: mf 0..3, nf 0..3

    // W loader: chunk c covers k = c*128 + sub*64 (c=8: one sub only, k 1024..1087)
    auto issueW = [&](int c, int st) {
        const int nsub = (c == 8) ? 1 : 2;
        for (int s = 0; s < nsub; ++s) {
            const uint32_t sb = sbase + SM_STG + st * STAGE_B + A_TILE_B + s * B_SUB_B;
            const __half* wp = Bw + (size_t)(c * 128 + s * 64);
            #pragma unroll
            for (int i = 0; i < 4; ++i) {
                const int idx = i * 256 + tid;
                const int row = idx >> 3, ch = idx & 7;
                cp16(sb + SWZ(row * 128 + ch * 16), wp + (size_t)row * KTOT + ch * 8);
            }
        }
    };

    #pragma unroll 1
    for (int t = 0; t < NSTEPS; ++t) {
        const __half* hi = (t & 1) ? g_hB : g_hA;
        __half* ho       = (t & 1) ? g_hA : g_hB;
        const __half* xp;
        int xstride;
        if (t < TIN) { xp = g_in + (size_t)t * FDIM; xstride = TIN * FDIM; }
        else         { xp = g_xd; xstride = FDIM; }

        auto issueA = [&](int c, int st) {
            const int nsub = (c == 8) ? 1 : 2;
            for (int s = 0; s < nsub; ++s) {
                const __half* ap;
                int lda;
                if (c < 8) { ap = hi + (size_t)m0 * UNITS + c * 128 + s * 64; lda = UNITS; }
                else       { ap = xp + (size_t)m0 * xstride;                  lda = xstride; }
                const uint32_t sb = sbase + SM_STG + st * STAGE_B + s * A_SUB_B;
                #pragma unroll
                for (int i = 0; i < 4; ++i) {
                    const int idx = i * 256 + tid;
                    const int row = idx >> 3, ch = idx & 7;
                    cp16(sb + SWZ(row * 128 + ch * 16), ap + (size_t)row * lda + ch * 8);
                }
            }
        };

        int c0;
        if (t == 0) { c0 = 8; issueA(8, 0); issueW(8, 0); cp_commit(); }  // h=0: x chunk only
        else        { c0 = 0; issueA(0, 0); cp_commit(); }                // W0 pre-issued last step

        #pragma unroll
        for (int i = 0; i < 4; ++i)
            #pragma unroll
            for (int j = 0; j < 4; ++j)
                #pragma unroll
                for (int r = 0; r < 4; ++r) acc[i][j][r] = 0.f;

        #pragma unroll 1
        for (int c = c0; c < NCHUNK; ++c) {
            const int st = c & 1;
            cp_wait<0>();
            __syncthreads();
            if (c + 1 < NCHUNK) {
                if (c + 1 == 8 && t >= TIN) {
                    // x tile = dense outputs of step t-1; wait for all dense CTAs
                    const int tgt = NBLK * (t - TIN + 1);
                    volatile const int* vp = (volatile const int*)&g_xflag;
                    while (*vp < tgt) __nanosleep(32);
                    __threadfence();
                }
                issueA(c + 1, st ^ 1);
                issueW(c + 1, st ^ 1);
                cp_commit();
            }

            const uint32_t stg = sbase + SM_STG + st * STAGE_B;
            const int nk = (c == 8) ? 4 : 8;

            // register double-buffered fragment pipeline across k16
            uint32_t ah[2][4][4], bh[2][2][4];
            #pragma unroll
            for (int mf = 0; mf < 4; ++mf)
                ldm4(ah[0][mf], stg + SWZ((a_r + mf * 16) * 128 + a_cs));
            #pragma unroll
            for (int p = 0; p < 2; ++p)
                ldm4(bh[0][p], stg + A_TILE_B + SWZ((b_r + p * 16) * 128 + b_cs));

            #pragma unroll 4
            for (int k16 = 0; k16 < nk; ++k16) {
                const int buf = k16 & 1;
                if (k16 + 1 < nk) {
                    const int nb = buf ^ 1;
                    const int sub = (k16 + 1) >> 2, kb = ((k16 + 1) & 3) * 32;
                    #pragma unroll
                    for (int mf = 0; mf < 4; ++mf)
                        ldm4(ah[nb][mf], stg + sub * A_SUB_B + SWZ((a_r + mf * 16) * 128 + kb + a_cs));
                    #pragma unroll
                    for (int p = 0; p < 2; ++p)
                        ldm4(bh[nb][p], stg + A_TILE_B + sub * B_SUB_B + SWZ((b_r + p * 16) * 128 + kb + b_cs));
                }
                #pragma unroll
                for (int mf = 0; mf < 4; ++mf)
                    #pragma unroll
                    for (int nf = 0; nf < 4; ++nf)
                        mma16816(acc[mf][nf], ah[buf][mf], &bh[buf][nf >> 1][(nf & 1) * 2]);
            }
        }

        // ---- epilogue: z scratch overlays stage 1 (last chunk c=8 computed from stage 0) ----
        float* zs = (float*)(smem + SM_ZS);
        __syncthreads();
        {
            const int gr = lane >> 2, gcn = (lane & 3) * 2;
            #pragma unroll
            for (int mf = 0; mf < 4; ++mf)
                #pragma unroll
                for (int nf = 0; nf < 4; ++nf) {
                    const int row = warp_m * 64 + mf * 16 + gr;
                    const int col = warp_n * 32 + nf * 8 + gcn;
                    *(float2*)&zs[row * 132 + col]       = make_float2(acc[mf][nf][0], acc[mf][nf][1]);
                    *(float2*)&zs[(row + 8) * 132 + col] = make_float2(acc[mf][nf][2], acc[mf][nf][3]);
                }
        }
        __syncthreads();
        {
            const int m  = tid >> 1;            // 0..127
            const int ub = (tid & 1) * 16;      // local unit base: 0 or 16
            const float4* zrow  = (const float4*)&zs[m * 132];
            const float4* bias4 = (const float4*)smem;
            const size_t idx0 = (size_t)(m0 + m) * UNITS + u0 + ub;
            __align__(16) __half hh[16];
            #pragma unroll
            for (int j = 0; j < 16; ++j) {
                const int ul = ub + j;
                const float4 z4 = zrow[ul];
                const float4 bb = bias4[ul];
                const float zi = z4.x + bb.x;
                const float zf = z4.y + bb.y;
                const float zg = z4.z + bb.z;
                const float zo = z4.w + bb.w;
                const float cn = sigm(zf) * cf[j] + sigm(zi) * ftanh(zg);
                cf[j] = cn;
                const float h = sigm(zo) * ftanh(cn);
                hh[j] = __float2half(h);
            }
            *(uint4*)(ho + idx0)     = *(const uint4*)&hh[0];
            *(uint4*)(ho + idx0 + 8) = *(const uint4*)&hh[8];
        }

        if (t + 1 < NSTEPS) { issueW(0, 0); cp_commit(); }   // prefetch next step's W0 across the barrier
        grid_barrier(bx, ++lgen);

        // ---- dense head: ALL CTAs, 4 batches x 64 features each (~1.5us, uniform) ----
        if (t >= TIN - 1) {
            const int ds = t - (TIN - 1);
            const int b = flat * 4 + (tid >> 6);
            const int f = tid & 63;
            const uint2* hp = (const uint2*)(ho + (size_t)b * UNITS);
            float a0 = 0.f;
            #pragma unroll 4
            for (int kq = 0; kq < UNITS / 4; ++kq) {
                const uint2 hv = __ldcg(hp + kq);
                const float2 h01 = __half22float2(*reinterpret_cast<const __half2*>(&hv.x));
                const float2 h23 = __half22float2(*reinterpret_cast<const __half2*>(&hv.y));
                const float* w = Wd + (size_t)kq * 4 * FDIM;
                a0 = fmaf(h01.x, w[f], a0);
                a0 = fmaf(h01.y, w[64 + f], a0);
                a0 = fmaf(h23.x, w[128 + f], a0);
                a0 = fmaf(h23.y, w[192 + f], a0);
            }
            const float p = a0 + bd[f];
            out[(size_t)b * (OUT_STEPS * FDIM) + (size_t)ds * FDIM + f] = p;
            g_xd[(size_t)b * FDIM + f] = __float2half(p);
            __syncthreads();
            __threadfence();
            if (tid == 0) atomicAdd(&g_xflag, 1);
        }
    }
}

// ---------------- preprocessing: coalesced tiled transpose to fp16 ----------------
__global__ __launch_bounds__(256)
void prep_weights(const float* __restrict__ Wk, const float* __restrict__ Wr,
                  const float* __restrict__ b) {
    __shared__ float tile[64][65];            // [n'_loc][k_loc]
    const int k0 = blockIdx.x * 64;
    const int u0 = blockIdx.y * 16;
    const int r  = threadIdx.x >> 2;
    const int cq = threadIdx.x & 3;
    const int k  = k0 + r;
    #pragma unroll
    for (int g = 0; g < 4; ++g) {
        const int col = g * UNITS + u0 + cq * 4;
        float4 v;
        if (k < UNITS) v = *(const float4*)(Wr + (size_t)k * NGATE + col);
        else           v = *(const float4*)(Wk + (size_t)(k - UNITS) * NGATE + col);
        tile[(cq * 4 + 0) * 4 + g][r] = v.x;
        tile[(cq * 4 + 1) * 4 + g][r] = v.y;
        tile[(cq * 4 + 2) * 4 + g][r] = v.z;
        tile[(cq * 4 + 3) * 4 + g][r] = v.w;
    }
    if (blockIdx.x == 0 && blockIdx.y == 0)
        for (int i = threadIdx.x; i < NGATE; i += 256)
            g_b2[i] = b[(i & 3) * UNITS + (i >> 2)];
    __syncthreads();
    const int nl = threadIdx.x >> 2;
    const int kk = (threadIdx.x & 3) * 16;
    const size_t ng = (size_t)(blockIdx.y * 64 + nl);
    __align__(16) __half hb[16];
    #pragma unroll
    for (int j = 0; j < 16; ++j)
        hb[j] = __float2half(tile[nl][kk + j]);
    *(uint4*)(g_Wt + ng * KTOT + k0 + kk)     = *(const uint4*)&hb[0];
    *(uint4*)(g_Wt + ng * KTOT + k0 + kk + 8) = *(const uint4*)&hb[8];
}

__global__ void prep_inputs(const float* __restrict__ inp) {
    const size_t idx = (size_t)blockIdx.x * blockDim.x + threadIdx.x;
    if (idx < (size_t)BSZ * TIN * FDIM)
        g_in[idx] = __float2half(inp[idx]);
}

// ---------------- launch ----------------
extern "C" void kernel_launch(void* const* d_in, const int* in_sizes, int n_in,
                              void* d_out, int out_size)
{
    const float* inputs = (const float*)d_in[0];
    const float* Wk     = (const float*)d_in[1];
    const float* Wr     = (const float*)d_in[2];
    const float* bias   = (const float*)d_in[3];
    const float* Wd     = (const float*)d_in[4];
    const float* bd     = (const float*)d_in[5];
    float* out = (float*)d_out;

    static bool attr_done = false;
    if (!attr_done) {
        cudaFuncSetAttribute(lstm_persist, cudaFuncAttributeMaxDynamicSharedMemorySize, SM_TOTAL);
        attr_done = true;
    }

    void* bar1_addr; void* bar2_addr; void* xflag_addr;
    cudaGetSymbolAddress(&bar1_addr, g_bar1);
    cudaGetSymbolAddress(&bar2_addr, g_bar2);
    cudaGetSymbolAddress(&xflag_addr, g_xflag);
    cudaMemsetAsync(bar1_addr, 0, 4 * 32 * sizeof(unsigned));
    cudaMemsetAsync(bar2_addr, 0, 32 * sizeof(unsigned));
    cudaMemsetAsync(xflag_addr, 0, sizeof(int));

    prep_weights<<<dim3(17, 64), 256>>>(Wk, Wr, bias);
    {
        const size_t ni = (size_t)BSZ * TIN * FDIM;
        prep_inputs<<<(unsigned)((ni + 255) / 256), 256>>>(inputs);
    }

    lstm_persist<<<dim3(4, 32), 256, SM_TOTAL>>>(Wd, bd, out);
}